// round 16
// baseline (speedup 1.0000x reference)
#include <cuda_runtime.h>
#include <cuda_bf16.h>
#include <cuda_fp16.h>
#include <cstdint>

#define B_ 2048
#define T_ 256
#define F_ 64
#define H_ 32
#define G_ 96

// scratch: xg[B*T][96] fp16 (100 MB)
__device__ __half g_xg[(size_t)B_ * T_ * G_];

__device__ __forceinline__ uint32_t smem_u32(const void* p) {
    uint32_t a;
    asm("{ .reg .u64 t; cvta.to.shared.u64 t, %1; cvt.u32.u64 %0, t; }" : "=r"(a) : "l"(p));
    return a;
}
__device__ __forceinline__ float tanh_fast(float v) {
    float y; asm("tanh.approx.f32 %0, %1;" : "=f"(y) : "f"(v)); return y;
}
__device__ __forceinline__ float sigmoid_fast(float a) {
    return fmaf(tanh_fast(0.5f * a), 0.5f, 0.5f);
}
__device__ __forceinline__ uint64_t ffma2(uint64_t a, uint64_t b, uint64_t c) {
    uint64_t d;
    asm("fma.rn.f32x2 %0, %1, %2, %3;" : "=l"(d) : "l"(a), "l"(b), "l"(c));
    return d;
}
__device__ __forceinline__ float f2lo(uint64_t v) { return __uint_as_float((uint32_t)v); }
__device__ __forceinline__ float f2hi(uint64_t v) { return __uint_as_float((uint32_t)(v >> 32)); }
__device__ __forceinline__ uint32_t pack_bf16(float a, float b) {
    __nv_bfloat162 t = __floats2bfloat162_rn(a, b);
    return *reinterpret_cast<uint32_t*>(&t);
}

// ================= Phase 1: xg = x @ W_ih^T + b_ih  (mma.sync bf16, 3-pass split) ===========
#define PM 128
#define AROW 144
#define AH_OFF 0
#define AL_OFF (PM * AROW)
#define BH_OFF (2 * PM * AROW)
#define BL_OFF (BH_OFF + G_ * AROW)
#define SMEM_P1 (BL_OFF + G_ * AROW)
#define STRIDE_ST 100

__device__ __forceinline__ void mma_bf16(float* d, uint32_t a0, uint32_t a1, uint32_t a2,
                                         uint32_t a3, uint32_t b0, uint32_t b1) {
    asm("mma.sync.aligned.m16n8k16.row.col.f32.bf16.bf16.f32 "
        "{%0,%1,%2,%3}, {%4,%5,%6,%7}, {%8,%9}, {%0,%1,%2,%3};"
        : "+f"(d[0]), "+f"(d[1]), "+f"(d[2]), "+f"(d[3])
        : "r"(a0), "r"(a1), "r"(a2), "r"(a3), "r"(b0), "r"(b1));
}
__device__ __forceinline__ void split4(float4 v, uint2& hp, uint2& lp) {
    __nv_bfloat16 h0 = __float2bfloat16(v.x), h1 = __float2bfloat16(v.y);
    __nv_bfloat16 h2 = __float2bfloat16(v.z), h3 = __float2bfloat16(v.w);
    hp.x = pack_bf16(__bfloat162float(h0), __bfloat162float(h1));
    hp.y = pack_bf16(__bfloat162float(h2), __bfloat162float(h3));
    lp.x = pack_bf16(v.x - __bfloat162float(h0), v.y - __bfloat162float(h1));
    lp.y = pack_bf16(v.z - __bfloat162float(h2), v.w - __bfloat162float(h3));
}

__global__ __launch_bounds__(256, 3)
void proj_kernel(const float* __restrict__ x,
                 const float* __restrict__ W_ih,
                 const float* __restrict__ b_ih,
                 __half* __restrict__ xg)
{
    extern __shared__ __align__(16) char dsm[];
    __shared__ __align__(16) float sbias[G_];

    const int tid  = threadIdx.x;
    const int wid  = tid >> 5;
    const int lane = tid & 31;
    const int g    = lane >> 2;
    const int tg   = lane & 3;
    const size_t base = (size_t)blockIdx.x * PM;

    {
        const float4* xin = reinterpret_cast<const float4*>(x + base * F_);
        #pragma unroll
        for (int it = 0; it < PM * F_ / 4 / 256; it++) {
            int i = tid + it * 256;
            float4 v = xin[i];
            int row = i >> 4, c4 = i & 15;
            uint2 hp, lp; split4(v, hp, lp);
            uint32_t off = row * AROW + c4 * 8;
            *reinterpret_cast<uint2*>(dsm + AH_OFF + off) = hp;
            *reinterpret_cast<uint2*>(dsm + AL_OFF + off) = lp;
        }
    }
    {
        const float4* win = reinterpret_cast<const float4*>(W_ih);
        #pragma unroll
        for (int it = 0; it < G_ * F_ / 4 / 256; it++) {
            int i = tid + it * 256;
            float4 v = win[i];
            int row = i >> 4, c4 = i & 15;
            uint2 hp, lp; split4(v, hp, lp);
            uint32_t off = row * AROW + c4 * 8;
            *reinterpret_cast<uint2*>(dsm + BH_OFF + off) = hp;
            *reinterpret_cast<uint2*>(dsm + BL_OFF + off) = lp;
        }
    }
    if (tid < G_) sbias[tid] = b_ih[tid];
    __syncthreads();

    const int m0 = wid * 16;
    float acc[12][4];
    #pragma unroll
    for (int n = 0; n < 12; n++)
        #pragma unroll
        for (int q = 0; q < 4; q++) acc[n][q] = 0.f;

    const uint32_t arow0 = (m0 + g) * AROW;
    const uint32_t arow1 = (m0 + g + 8) * AROW;

    #pragma unroll
    for (int k = 0; k < 4; k++) {
        const uint32_t c0 = (k * 16 + 2 * tg) * 2;
        const uint32_t c1 = c0 + 16;
        uint32_t ah0 = *reinterpret_cast<const uint32_t*>(dsm + AH_OFF + arow0 + c0);
        uint32_t ah1 = *reinterpret_cast<const uint32_t*>(dsm + AH_OFF + arow1 + c0);
        uint32_t ah2 = *reinterpret_cast<const uint32_t*>(dsm + AH_OFF + arow0 + c1);
        uint32_t ah3 = *reinterpret_cast<const uint32_t*>(dsm + AH_OFF + arow1 + c1);
        uint32_t al0 = *reinterpret_cast<const uint32_t*>(dsm + AL_OFF + arow0 + c0);
        uint32_t al1 = *reinterpret_cast<const uint32_t*>(dsm + AL_OFF + arow1 + c0);
        uint32_t al2 = *reinterpret_cast<const uint32_t*>(dsm + AL_OFF + arow0 + c1);
        uint32_t al3 = *reinterpret_cast<const uint32_t*>(dsm + AL_OFF + arow1 + c1);
        #pragma unroll
        for (int n = 0; n < 12; n++) {
            const uint32_t brow = (n * 8 + g) * AROW;
            uint32_t bh0 = *reinterpret_cast<const uint32_t*>(dsm + BH_OFF + brow + c0);
            uint32_t bh1 = *reinterpret_cast<const uint32_t*>(dsm + BH_OFF + brow + c1);
            uint32_t bl0 = *reinterpret_cast<const uint32_t*>(dsm + BL_OFF + brow + c0);
            uint32_t bl1 = *reinterpret_cast<const uint32_t*>(dsm + BL_OFF + brow + c1);
            mma_bf16(acc[n], ah0, ah1, ah2, ah3, bh0, bh1);
            mma_bf16(acc[n], ah0, ah1, ah2, ah3, bl0, bl1);
            mma_bf16(acc[n], al0, al1, al2, al3, bh0, bh1);
        }
    }
    __syncthreads();

    float* stage = reinterpret_cast<float*>(dsm);
    {
        #pragma unroll
        for (int n = 0; n < 12; n++) {
            int c = n * 8 + 2 * tg;
            float2* p0 = reinterpret_cast<float2*>(&stage[(m0 + g) * STRIDE_ST + c]);
            float2* p1 = reinterpret_cast<float2*>(&stage[(m0 + g + 8) * STRIDE_ST + c]);
            *p0 = make_float2(acc[n][0], acc[n][1]);
            *p1 = make_float2(acc[n][2], acc[n][3]);
        }
    }
    __syncthreads();

    // ---- coalesced fp16 store with bias add (8 halves = 16B per thread per iter) ----
    {
        uint4* outp = reinterpret_cast<uint4*>(xg + base * G_);
        #pragma unroll
        for (int it = 0; it < PM * G_ / 8 / 256; it++) {
            int i = tid + it * 256;
            int e = 8 * i;
            int r = e / G_, c = e % G_;
            const float* sp = &stage[r * STRIDE_ST + c];
            const float* bp = &sbias[c];
            __half2 h0 = __floats2half2_rn(sp[0] + bp[0], sp[1] + bp[1]);
            __half2 h1 = __floats2half2_rn(sp[2] + bp[2], sp[3] + bp[3]);
            __half2 h2 = __floats2half2_rn(sp[4] + bp[4], sp[5] + bp[5]);
            __half2 h3 = __floats2half2_rn(sp[6] + bp[6], sp[7] + bp[7]);
            uint4 v;
            v.x = *reinterpret_cast<uint32_t*>(&h0);
            v.y = *reinterpret_cast<uint32_t*>(&h1);
            v.z = *reinterpret_cast<uint32_t*>(&h2);
            v.w = *reinterpret_cast<uint32_t*>(&h3);
            outp[i] = v;
        }
    }
}

// ========== Phase 2: recurrence — 4 rows per warp, 1-warp CTAs, fp16 cp.async ring ==========
#define ROWS 4
#define NSLOT 8
#define PF 7
#define SLOTB (ROWS * G_ * 2)     // 768 bytes per ring slot

__global__ __launch_bounds__(32, 8)
void gru_kernel(const __half* __restrict__ xg,
                const float* __restrict__ W_hh,
                const float* __restrict__ b_hh,
                const float* __restrict__ W_head,
                const float* __restrict__ b_head,
                float* __restrict__ out)
{
    __shared__ __align__(16) __half ring[NSLOT][ROWS][G_];  // 6 KB
    __shared__ __align__(16) float sh[2][ROWS][H_];         // 1 KB

    const int j    = threadIdx.x & 31;
    const int row0 = blockIdx.x * ROWS;

    // shared per-lane recurrent weights (f32x2 pairs)
    uint64_t Wr2[H_ / 2], Wz2[H_ / 2], Wn2[H_ / 2];
    {
        const ulonglong2* pr = reinterpret_cast<const ulonglong2*>(W_hh + (j)          * H_);
        const ulonglong2* pz = reinterpret_cast<const ulonglong2*>(W_hh + (H_ + j)     * H_);
        const ulonglong2* pn = reinterpret_cast<const ulonglong2*>(W_hh + (2 * H_ + j) * H_);
        #pragma unroll
        for (int i = 0; i < H_ / 4; i++) {
            ulonglong2 a = pr[i], b = pz[i], c = pn[i];
            Wr2[2*i] = a.x; Wr2[2*i+1] = a.y;
            Wz2[2*i] = b.x; Wz2[2*i+1] = b.y;
            Wn2[2*i] = c.x; Wn2[2*i+1] = c.y;
        }
    }
    const uint64_t br2 = (uint64_t)__float_as_uint(b_hh[j]);
    const uint64_t bz2 = (uint64_t)__float_as_uint(b_hh[H_ + j]);
    const uint64_t bn2 = (uint64_t)__float_as_uint(b_hh[2 * H_ + j]);

    // per-lane cp.async chunks: slot = 768B = 48 x 16B; chunk ch -> row ch/12, 16B-off ch%12.
    // lane j handles chunks j (all lanes) and j+32 (lanes 0..15).
    const __half* srcb[2];
    uint32_t      dsto[2];
    #pragma unroll
    for (int c = 0; c < 2; c++) {
        int ch = j + 32 * c;
        int r  = ch / 12;          // 0..3
        int wo = ch % 12;          // 16B unit within row (8 halves)
        srcb[c] = xg + ((size_t)(row0 + (r & 3)) * T_) * G_ + wo * 8;
        dsto[c] = (uint32_t)ch * 16;
    }
    const uint32_t rb = smem_u32(&ring[0][0][0]);

    // preload slots 0..PF-1
    #pragma unroll
    for (int p = 0; p < PF; p++) {
        {
            uint32_t dst = rb + (uint32_t)p * SLOTB + dsto[0];
            const __half* src = srcb[0] + (size_t)p * G_;
            asm volatile("cp.async.cg.shared.global [%0], [%1], 16;" :: "r"(dst), "l"(src));
        }
        if (j < 16) {
            uint32_t dst = rb + (uint32_t)p * SLOTB + dsto[1];
            const __half* src = srcb[1] + (size_t)p * G_;
            asm volatile("cp.async.cg.shared.global [%0], [%1], 16;" :: "r"(dst), "l"(src));
        }
        asm volatile("cp.async.commit_group;" ::: "memory");
    }

    #pragma unroll
    for (int r = 0; r < ROWS; r++) sh[0][r][j] = 0.f;
    float h[ROWS];
    #pragma unroll
    for (int r = 0; r < ROWS; r++) h[r] = 0.f;
    __syncwarp();

    #pragma unroll 1
    for (int t = 0; t < T_; t++) {
        // prefetch slot t+PF
        {
            int ft = t + PF;
            if (ft < T_) {
                uint32_t dst = rb + (uint32_t)(ft & (NSLOT - 1)) * SLOTB + dsto[0];
                const __half* src = srcb[0] + (size_t)ft * G_;
                asm volatile("cp.async.cg.shared.global [%0], [%1], 16;" :: "r"(dst), "l"(src));
                if (j < 16) {
                    uint32_t dst1 = rb + (uint32_t)(ft & (NSLOT - 1)) * SLOTB + dsto[1];
                    const __half* src1 = srcb[1] + (size_t)ft * G_;
                    asm volatile("cp.async.cg.shared.global [%0], [%1], 16;" :: "r"(dst1), "l"(src1));
                }
            }
            asm volatile("cp.async.commit_group;" ::: "memory");
            asm volatile("cp.async.wait_group 6;" ::: "memory");
            __syncwarp();
        }

        // gate inputs for all rows (fp16 -> fp32)
        float xr[ROWS], xz[ROWS], xn[ROWS];
        #pragma unroll
        for (int r = 0; r < ROWS; r++) {
            const __half* xs = &ring[t & (NSLOT - 1)][r][0];
            xr[r] = __half2float(xs[j]);
            xz[r] = __half2float(xs[H_ + j]);
            xn[r] = __half2float(xs[2 * H_ + j]);
        }

        // 12 independent FFMA2 chains (3 gates x 4 rows, depth 16)
        uint64_t ar[ROWS], az[ROWS], an[ROWS];
        #pragma unroll
        for (int r = 0; r < ROWS; r++) { ar[r] = br2; az[r] = bz2; an[r] = bn2; }

        const ulonglong2* hp[ROWS];
        #pragma unroll
        for (int r = 0; r < ROWS; r++)
            hp[r] = reinterpret_cast<const ulonglong2*>(sh[t & 1][r]);

        #pragma unroll
        for (int i = 0; i < H_ / 4; i++) {
            #pragma unroll
            for (int r = 0; r < ROWS; r++) {
                ulonglong2 hv = hp[r][i];
                ar[r] = ffma2(hv.x, Wr2[2*i],   ar[r]);
                az[r] = ffma2(hv.x, Wz2[2*i],   az[r]);
                an[r] = ffma2(hv.x, Wn2[2*i],   an[r]);
                ar[r] = ffma2(hv.y, Wr2[2*i+1], ar[r]);
                az[r] = ffma2(hv.y, Wz2[2*i+1], az[r]);
                an[r] = ffma2(hv.y, Wn2[2*i+1], an[r]);
            }
        }

        #pragma unroll
        for (int r = 0; r < ROWS; r++) {
            float arf = f2lo(ar[r]) + f2hi(ar[r]);
            float azf = f2lo(az[r]) + f2hi(az[r]);
            float anf = f2lo(an[r]) + f2hi(an[r]);
            float rg = sigmoid_fast(xr[r] + arf);
            float zg = sigmoid_fast(xz[r] + azf);
            float ng = tanh_fast(fmaf(rg, anf, xn[r]));
            h[r] = fmaf(zg, h[r] - ng, ng);
            sh[(t + 1) & 1][r][j] = h[r];
        }
        __syncwarp();
    }

    // head for all rows
    float wv = W_head[j];
    float v[ROWS];
    #pragma unroll
    for (int r = 0; r < ROWS; r++) v[r] = h[r] * wv;
    #pragma unroll
    for (int o = 16; o > 0; o >>= 1) {
        #pragma unroll
        for (int r = 0; r < ROWS; r++)
            v[r] += __shfl_xor_sync(0xffffffffu, v[r], o);
    }
    if (j == 0) {
        float bh = b_head[0];
        #pragma unroll
        for (int r = 0; r < ROWS; r++)
            out[row0 + r] = sigmoid_fast(v[r] + bh);
    }
}

extern "C" void kernel_launch(void* const* d_in, const int* in_sizes, int n_in,
                              void* d_out, int out_size)
{
    const float* x      = (const float*)d_in[0];
    const float* W_ih   = (const float*)d_in[1];
    const float* W_hh   = (const float*)d_in[2];
    const float* b_ih   = (const float*)d_in[3];
    const float* b_hh   = (const float*)d_in[4];
    const float* W_head = (const float*)d_in[5];
    const float* b_head = (const float*)d_in[6];
    float* out = (float*)d_out;

    __half* xg;
    cudaGetSymbolAddress((void**)&xg, g_xg);

    cudaFuncSetAttribute(proj_kernel, cudaFuncAttributeMaxDynamicSharedMemorySize, SMEM_P1);
    proj_kernel<<<(B_ * T_) / PM, 256, SMEM_P1>>>(x, W_ih, b_ih, xg);
    gru_kernel<<<B_ / ROWS, 32>>>(xg, W_hh, b_hh, W_head, b_head, out);
}

// round 17
// speedup vs baseline: 1.2450x; 1.2450x over previous
#include <cuda_runtime.h>
#include <cuda_bf16.h>
#include <cuda_fp16.h>
#include <cstdint>

#define B_ 2048
#define T_ 256
#define F_ 64
#define H_ 32
#define G_ 96

// scratch: xg[B*T][96] fp32 (201 MB)
__device__ float g_xg[(size_t)B_ * T_ * G_];

__device__ __forceinline__ uint32_t smem_u32(const void* p) {
    uint32_t a;
    asm("{ .reg .u64 t; cvta.to.shared.u64 t, %1; cvt.u32.u64 %0, t; }" : "=r"(a) : "l"(p));
    return a;
}
__device__ __forceinline__ float tanh_fast(float v) {
    float y; asm("tanh.approx.f32 %0, %1;" : "=f"(y) : "f"(v)); return y;
}
__device__ __forceinline__ float sigmoid_fast(float a) {
    return fmaf(tanh_fast(0.5f * a), 0.5f, 0.5f);
}
__device__ __forceinline__ uint32_t pack_bf16(float a, float b) {
    __nv_bfloat162 t = __floats2bfloat162_rn(a, b);
    return *reinterpret_cast<uint32_t*>(&t);
}
__device__ __forceinline__ uint32_t pack_f16(float a, float b) {
    __half2 t = __floats2half2_rn(a, b);
    return *reinterpret_cast<uint32_t*>(&t);
}

// ================= Phase 1: xg = x @ W_ih^T + b_ih  (mma.sync bf16, 3-pass split) ===========
#define PM 128
#define AROW 144
#define AH_OFF 0
#define AL_OFF (PM * AROW)
#define BH_OFF (2 * PM * AROW)
#define BL_OFF (BH_OFF + G_ * AROW)
#define SMEM_P1 (BL_OFF + G_ * AROW)
#define STRIDE_ST 100

__device__ __forceinline__ void mma_bf16(float* d, uint32_t a0, uint32_t a1, uint32_t a2,
                                         uint32_t a3, uint32_t b0, uint32_t b1) {
    asm("mma.sync.aligned.m16n8k16.row.col.f32.bf16.bf16.f32 "
        "{%0,%1,%2,%3}, {%4,%5,%6,%7}, {%8,%9}, {%0,%1,%2,%3};"
        : "+f"(d[0]), "+f"(d[1]), "+f"(d[2]), "+f"(d[3])
        : "r"(a0), "r"(a1), "r"(a2), "r"(a3), "r"(b0), "r"(b1));
}
__device__ __forceinline__ void mma_f16(float* d, const uint32_t* a, uint32_t b0, uint32_t b1) {
    asm("mma.sync.aligned.m16n8k16.row.col.f32.f16.f16.f32 "
        "{%0,%1,%2,%3}, {%4,%5,%6,%7}, {%8,%9}, {%0,%1,%2,%3};"
        : "+f"(d[0]), "+f"(d[1]), "+f"(d[2]), "+f"(d[3])
        : "r"(a[0]), "r"(a[1]), "r"(a[2]), "r"(a[3]), "r"(b0), "r"(b1));
}
__device__ __forceinline__ void split4(float4 v, uint2& hp, uint2& lp) {
    __nv_bfloat16 h0 = __float2bfloat16(v.x), h1 = __float2bfloat16(v.y);
    __nv_bfloat16 h2 = __float2bfloat16(v.z), h3 = __float2bfloat16(v.w);
    hp.x = pack_bf16(__bfloat162float(h0), __bfloat162float(h1));
    hp.y = pack_bf16(__bfloat162float(h2), __bfloat162float(h3));
    lp.x = pack_bf16(v.x - __bfloat162float(h0), v.y - __bfloat162float(h1));
    lp.y = pack_bf16(v.z - __bfloat162float(h2), v.w - __bfloat162float(h3));
}

__global__ __launch_bounds__(256, 3)
void proj_kernel(const float* __restrict__ x,
                 const float* __restrict__ W_ih,
                 const float* __restrict__ b_ih,
                 float* __restrict__ xg)
{
    extern __shared__ __align__(16) char dsm[];
    __shared__ __align__(16) float sbias[G_];

    const int tid  = threadIdx.x;
    const int wid  = tid >> 5;
    const int lane = tid & 31;
    const int g    = lane >> 2;
    const int tg   = lane & 3;
    const size_t base = (size_t)blockIdx.x * PM;

    {
        const float4* xin = reinterpret_cast<const float4*>(x + base * F_);
        #pragma unroll
        for (int it = 0; it < PM * F_ / 4 / 256; it++) {
            int i = tid + it * 256;
            float4 v = xin[i];
            int row = i >> 4, c4 = i & 15;
            uint2 hp, lp; split4(v, hp, lp);
            uint32_t off = row * AROW + c4 * 8;
            *reinterpret_cast<uint2*>(dsm + AH_OFF + off) = hp;
            *reinterpret_cast<uint2*>(dsm + AL_OFF + off) = lp;
        }
    }
    {
        const float4* win = reinterpret_cast<const float4*>(W_ih);
        #pragma unroll
        for (int it = 0; it < G_ * F_ / 4 / 256; it++) {
            int i = tid + it * 256;
            float4 v = win[i];
            int row = i >> 4, c4 = i & 15;
            uint2 hp, lp; split4(v, hp, lp);
            uint32_t off = row * AROW + c4 * 8;
            *reinterpret_cast<uint2*>(dsm + BH_OFF + off) = hp;
            *reinterpret_cast<uint2*>(dsm + BL_OFF + off) = lp;
        }
    }
    if (tid < G_) sbias[tid] = b_ih[tid];
    __syncthreads();

    const int m0 = wid * 16;
    float acc[12][4];
    #pragma unroll
    for (int n = 0; n < 12; n++)
        #pragma unroll
        for (int q = 0; q < 4; q++) acc[n][q] = 0.f;

    const uint32_t arow0 = (m0 + g) * AROW;
    const uint32_t arow1 = (m0 + g + 8) * AROW;

    #pragma unroll
    for (int k = 0; k < 4; k++) {
        const uint32_t c0 = (k * 16 + 2 * tg) * 2;
        const uint32_t c1 = c0 + 16;
        uint32_t ah0 = *reinterpret_cast<const uint32_t*>(dsm + AH_OFF + arow0 + c0);
        uint32_t ah1 = *reinterpret_cast<const uint32_t*>(dsm + AH_OFF + arow1 + c0);
        uint32_t ah2 = *reinterpret_cast<const uint32_t*>(dsm + AH_OFF + arow0 + c1);
        uint32_t ah3 = *reinterpret_cast<const uint32_t*>(dsm + AH_OFF + arow1 + c1);
        uint32_t al0 = *reinterpret_cast<const uint32_t*>(dsm + AL_OFF + arow0 + c0);
        uint32_t al1 = *reinterpret_cast<const uint32_t*>(dsm + AL_OFF + arow1 + c0);
        uint32_t al2 = *reinterpret_cast<const uint32_t*>(dsm + AL_OFF + arow0 + c1);
        uint32_t al3 = *reinterpret_cast<const uint32_t*>(dsm + AL_OFF + arow1 + c1);
        #pragma unroll
        for (int n = 0; n < 12; n++) {
            const uint32_t brow = (n * 8 + g) * AROW;
            uint32_t bh0 = *reinterpret_cast<const uint32_t*>(dsm + BH_OFF + brow + c0);
            uint32_t bh1 = *reinterpret_cast<const uint32_t*>(dsm + BH_OFF + brow + c1);
            uint32_t bl0 = *reinterpret_cast<const uint32_t*>(dsm + BL_OFF + brow + c0);
            uint32_t bl1 = *reinterpret_cast<const uint32_t*>(dsm + BL_OFF + brow + c1);
            mma_bf16(acc[n], ah0, ah1, ah2, ah3, bh0, bh1);
            mma_bf16(acc[n], ah0, ah1, ah2, ah3, bl0, bl1);
            mma_bf16(acc[n], al0, al1, al2, al3, bh0, bh1);
        }
    }
    __syncthreads();

    float* stage = reinterpret_cast<float*>(dsm);
    {
        #pragma unroll
        for (int n = 0; n < 12; n++) {
            int c = n * 8 + 2 * tg;
            float2* p0 = reinterpret_cast<float2*>(&stage[(m0 + g) * STRIDE_ST + c]);
            float2* p1 = reinterpret_cast<float2*>(&stage[(m0 + g + 8) * STRIDE_ST + c]);
            *p0 = make_float2(acc[n][0], acc[n][1]);
            *p1 = make_float2(acc[n][2], acc[n][3]);
        }
    }
    __syncthreads();

    {
        float4* outp = reinterpret_cast<float4*>(xg + base * G_);
        #pragma unroll
        for (int it = 0; it < PM * G_ / 4 / 256; it++) {
            int i = tid + it * 256;
            int e = 4 * i;
            int r = e / G_, c = e % G_;
            float4 bb = *reinterpret_cast<const float4*>(&sbias[c]);
            const float* sp = &stage[r * STRIDE_ST + c];
            float4 v;
            v.x = sp[0] + bb.x; v.y = sp[1] + bb.y;
            v.z = sp[2] + bb.z; v.w = sp[3] + bb.w;
            outp[i] = v;
        }
    }
}

// ========== Phase 2: recurrence via HMMA — 8 rows/warp, 1-warp CTAs ==========
// Per step: gates[96x8] = W_hh[96x32] @ h[32x8] as 6 m-tiles x 2 k-steps of
// m16n8k16 f16 (fp32 accum). W_hh lives in registers as A-fragments. h is
// exchanged through a padded fp16 smem buffer (bank-conflict-free).
#define ROWS 8
#define NSLOT 8
#define PF 7
#define RSTRIDE 100                    // floats per row in a ring slot (pad: conflict-free)
#define SLOTF (ROWS * RSTRIDE)         // 800 floats
#define SLOTB (SLOTF * 4)              // 3200 B
#define HSTRB 80                       // bytes per row in h16 (pad: conflict-free)

__global__ __launch_bounds__(32, 4)
void gru_kernel(const float* __restrict__ xg,
                const float* __restrict__ W_hh,
                const float* __restrict__ b_hh,
                const float* __restrict__ W_head,
                const float* __restrict__ b_head,
                float* __restrict__ out)
{
    __shared__ __align__(16) float ring[NSLOT * SLOTF];        // 25600 B
    __shared__ __align__(16) __half h16[ROWS * (HSTRB / 2)];   // 640 B

    const int j = threadIdx.x & 31;
    const int q = j >> 2;    // 0..7
    const int m = j & 3;     // 0..3
    const int row0 = blockIdx.x * ROWS;

    // ---- A-fragments: W_hh (fp16), 6 m-tiles x 2 k-steps x 4 regs ----
    uint32_t A[6][2][4];
    #pragma unroll
    for (int mt = 0; mt < 6; mt++) {
        #pragma unroll
        for (int kt = 0; kt < 2; kt++) {
            int r0 = 16 * mt + q;
            int c0 = 16 * kt + 2 * m;
            float2 v0 = *reinterpret_cast<const float2*>(W_hh + (r0)     * H_ + c0);
            float2 v1 = *reinterpret_cast<const float2*>(W_hh + (r0 + 8) * H_ + c0);
            float2 v2 = *reinterpret_cast<const float2*>(W_hh + (r0)     * H_ + c0 + 8);
            float2 v3 = *reinterpret_cast<const float2*>(W_hh + (r0 + 8) * H_ + c0 + 8);
            A[mt][kt][0] = pack_f16(v0.x, v0.y);
            A[mt][kt][1] = pack_f16(v1.x, v1.y);
            A[mt][kt][2] = pack_f16(v2.x, v2.y);
            A[mt][kt][3] = pack_f16(v3.x, v3.y);
        }
    }

    // per-lane biases / head weights for units u_i = q + 8i
    float br[4], bz[4], bn[4], wh[4];
    #pragma unroll
    for (int i = 0; i < 4; i++) {
        int u = q + 8 * i;
        br[i] = b_hh[u];
        bz[i] = b_hh[H_ + u];
        bn[i] = b_hh[2 * H_ + u];
        wh[i] = W_head[u];
    }

    // cp.async: slot = 192 16B-chunks; lane j owns chunks j+32c, c<6 (exact).
    const float* srcb[6];
    uint32_t     dsto[6];
    #pragma unroll
    for (int c = 0; c < 6; c++) {
        int ch = j + 32 * c;
        int r  = ch / 24;        // 0..7
        int wo = ch % 24;        // 16B unit within row
        srcb[c] = xg + ((size_t)(row0 + r) * T_) * G_ + wo * 4;
        dsto[c] = (uint32_t)r * (RSTRIDE * 4) + (uint32_t)wo * 16;
    }
    const uint32_t rb  = smem_u32(ring);
    const uint32_t hb  = smem_u32(h16);

    // preload slots 0..PF-1
    #pragma unroll
    for (int p = 0; p < PF; p++) {
        #pragma unroll
        for (int c = 0; c < 6; c++) {
            uint32_t dst = rb + (uint32_t)p * SLOTB + dsto[c];
            const float* src = srcb[c] + (size_t)p * G_;
            asm volatile("cp.async.cg.shared.global [%0], [%1], 16;" :: "r"(dst), "l"(src));
        }
        asm volatile("cp.async.commit_group;" ::: "memory");
    }

    // init h = 0 (regs h[i*2+e] for units u_i, batch cols n = 2m+e)
    float h[8];
    #pragma unroll
    for (int k = 0; k < 8; k++) h[k] = 0.f;
    #pragma unroll
    for (int e = 0; e < 2; e++)
        #pragma unroll
        for (int i = 0; i < 4; i++)
            h16[(2 * m + e) * (HSTRB / 2) + q + 8 * i] = __float2half(0.f);
    __syncwarp();

    // B-frag smem addresses (fixed per lane): row n = q, k pair base = 2m halves
    const uint32_t bb = hb + (uint32_t)q * HSTRB + (uint32_t)m * 4;

    #pragma unroll 1
    for (int t = 0; t < T_; t++) {
        // prefetch slot t+PF
        {
            int ft = t + PF;
            if (ft < T_) {
                #pragma unroll
                for (int c = 0; c < 6; c++) {
                    uint32_t dst = rb + (uint32_t)(ft & (NSLOT - 1)) * SLOTB + dsto[c];
                    const float* src = srcb[c] + (size_t)ft * G_;
                    asm volatile("cp.async.cg.shared.global [%0], [%1], 16;" :: "r"(dst), "l"(src));
                }
            }
            asm volatile("cp.async.commit_group;" ::: "memory");
            asm volatile("cp.async.wait_group 6;" ::: "memory");
            __syncwarp();
        }

        // B fragments: h16[row n=q][k] pairs; b[kt] = {k base, k base+8}
        uint32_t b0, b1, b2, b3;
        asm volatile("ld.shared.u32 %0, [%1];"      : "=r"(b0) : "r"(bb));
        asm volatile("ld.shared.u32 %0, [%1 + 16];" : "=r"(b1) : "r"(bb));
        asm volatile("ld.shared.u32 %0, [%1 + 32];" : "=r"(b2) : "r"(bb));
        asm volatile("ld.shared.u32 %0, [%1 + 48];" : "=r"(b3) : "r"(bb));

        // gates = W_hh @ h : 12 HMMA, fp32 accum
        float C[6][4];
        #pragma unroll
        for (int mt = 0; mt < 6; mt++) {
            C[mt][0] = 0.f; C[mt][1] = 0.f; C[mt][2] = 0.f; C[mt][3] = 0.f;
            mma_f16(C[mt], A[mt][0], b0, b1);
            mma_f16(C[mt], A[mt][1], b2, b3);
        }

        // x-gate loads + activations for 8 (unit,row) pairs
        const float* lb = ring + (t & (NSLOT - 1)) * SLOTF + 200 * m + q;
        #pragma unroll
        for (int e = 0; e < 2; e++) {
            #pragma unroll
            for (int i = 0; i < 4; i++) {
                float xr = lb[100 * e + 8 * i];
                float xz = lb[100 * e + 32 + 8 * i];
                float xn = lb[100 * e + 64 + 8 * i];
                float cr = C[(i >> 1)][2 * (i & 1) + e];
                float cz = C[2 + (i >> 1)][2 * (i & 1) + e];
                float cn = C[4 + (i >> 1)][2 * (i & 1) + e];
                float rg = sigmoid_fast(xr + cr + br[i]);
                float zg = sigmoid_fast(xz + cz + bz[i]);
                float ng = tanh_fast(fmaf(rg, cn + bn[i], xn));
                int idx = i * 2 + e;
                h[idx] = fmaf(zg, h[idx] - ng, ng);
            }
        }
        __syncwarp();   // all B-frag reads done before h16 overwrite

        #pragma unroll
        for (int e = 0; e < 2; e++)
            #pragma unroll
            for (int i = 0; i < 4; i++)
                h16[(2 * m + e) * (HSTRB / 2) + q + 8 * i] = __float2half(h[i * 2 + e]);
        __syncwarp();   // writes visible before next step's B-frag reads
    }

    // head: per lane partial over its 4 units for cols n = 2m, 2m+1
    float s0 = 0.f, s1 = 0.f;
    #pragma unroll
    for (int i = 0; i < 4; i++) {
        s0 = fmaf(wh[i], h[i * 2 + 0], s0);
        s1 = fmaf(wh[i], h[i * 2 + 1], s1);
    }
    // reduce over q (lanes with same m): strides 4, 8, 16
    #pragma unroll
    for (int o = 4; o <= 16; o <<= 1) {
        s0 += __shfl_xor_sync(0xffffffffu, s0, o);
        s1 += __shfl_xor_sync(0xffffffffu, s1, o);
    }
    if (j < 4) {
        float bh = b_head[0];
        out[row0 + 2 * j + 0] = sigmoid_fast(s0 + bh);
        out[row0 + 2 * j + 1] = sigmoid_fast(s1 + bh);
    }
}

extern "C" void kernel_launch(void* const* d_in, const int* in_sizes, int n_in,
                              void* d_out, int out_size)
{
    const float* x      = (const float*)d_in[0];
    const float* W_ih   = (const float*)d_in[1];
    const float* W_hh   = (const float*)d_in[2];
    const float* b_ih   = (const float*)d_in[3];
    const float* b_hh   = (const float*)d_in[4];
    const float* W_head = (const float*)d_in[5];
    const float* b_head = (const float*)d_in[6];
    float* out = (float*)d_out;

    float* xg;
    cudaGetSymbolAddress((void**)&xg, g_xg);

    cudaFuncSetAttribute(proj_kernel, cudaFuncAttributeMaxDynamicSharedMemorySize, SMEM_P1);
    proj_kernel<<<(B_ * T_) / PM, 256, SMEM_P1>>>(x, W_ih, b_ih, xg);
    gru_kernel<<<B_ / ROWS, 32>>>(xg, W_hh, b_hh, W_head, b_head, out);
}